// round 1
// baseline (speedup 1.0000x reference)
#include <cuda_runtime.h>
#include <math.h>

#define D_MODEL 512
#define N_HEADS 8
#define HEAD_DIM 64
#define BATCH 2
#define SEQ 2048
#define TOPK 64
#define M_TOT (BATCH*SEQ)      /* 4096 */
#define SCALE 0.125f

// ---------------- scratch (device globals: allocation-free rule) ----------------
__device__ float g_q[M_TOT * D_MODEL];
__device__ float g_k[M_TOT * D_MODEL];
__device__ float g_v[M_TOT * D_MODEL];
__device__ float g_oh[M_TOT * D_MODEL];
__device__ float g_attn[(size_t)BATCH * N_HEADS * SEQ * SEQ];   // 268 MB fallback if attn not in d_out

// ---------------- fp32 NT GEMM: C[m][n] = alpha * sum_k A[m][k]*B[n][k] + bias[n] ----------------
#define BM 128
#define BN 64
#define BK 16

__device__ __forceinline__ void gemm_nt_core(
    const float* __restrict__ A, int lda,
    const float* __restrict__ Bm, int ldb,
    float* __restrict__ C, int ldc,
    int K, float alpha, const float* __restrict__ bias,
    int bm, int bn)
{
    __shared__ float As[BK][BM];
    __shared__ float Bs[BK][BN];
    const int tid = threadIdx.x;          // 256 threads
    const int ty = tid >> 4;              // 0..15 (row group of 8)
    const int tx = tid & 15;              // 0..15 (col group of 4)

    float acc[8][4];
#pragma unroll
    for (int i = 0; i < 8; i++)
#pragma unroll
        for (int j = 0; j < 4; j++) acc[i][j] = 0.0f;

    const float* Abase = A + (size_t)(bm * BM) * lda;
    const float* Bbase = Bm + (size_t)(bn * BN) * ldb;

    for (int k0 = 0; k0 < K; k0 += BK) {
        // A tile: 128x16 = 512 float4, 2 per thread
#pragma unroll
        for (int r = 0; r < 2; r++) {
            int idx = tid + r * 256;
            int row = idx >> 2;
            int kc  = (idx & 3) << 2;
            float4 v = *(const float4*)(Abase + (size_t)row * lda + k0 + kc);
            As[kc + 0][row] = v.x;
            As[kc + 1][row] = v.y;
            As[kc + 2][row] = v.z;
            As[kc + 3][row] = v.w;
        }
        // B tile: 64x16 = 256 float4, 1 per thread
        {
            int row = tid >> 2;
            int kc  = (tid & 3) << 2;
            float4 v = *(const float4*)(Bbase + (size_t)row * ldb + k0 + kc);
            Bs[kc + 0][row] = v.x;
            Bs[kc + 1][row] = v.y;
            Bs[kc + 2][row] = v.z;
            Bs[kc + 3][row] = v.w;
        }
        __syncthreads();

#pragma unroll
        for (int kk = 0; kk < BK; kk++) {
            float4 alo = *(const float4*)&As[kk][ty * 8];
            float4 ahi = *(const float4*)&As[kk][ty * 8 + 4];
            float4 bb  = *(const float4*)&Bs[kk][tx * 4];
            float a[8] = {alo.x, alo.y, alo.z, alo.w, ahi.x, ahi.y, ahi.z, ahi.w};
            float b[4] = {bb.x, bb.y, bb.z, bb.w};
#pragma unroll
            for (int i = 0; i < 8; i++)
#pragma unroll
                for (int j = 0; j < 4; j++) acc[i][j] += a[i] * b[j];
        }
        __syncthreads();
    }

    const int row0 = bm * BM + ty * 8;
    const int col0 = bn * BN + tx * 4;
    float bvals[4] = {0.f, 0.f, 0.f, 0.f};
    if (bias) {
        bvals[0] = bias[col0 + 0]; bvals[1] = bias[col0 + 1];
        bvals[2] = bias[col0 + 2]; bvals[3] = bias[col0 + 3];
    }
#pragma unroll
    for (int i = 0; i < 8; i++) {
        float4 o;
        o.x = alpha * acc[i][0] + bvals[0];
        o.y = alpha * acc[i][1] + bvals[1];
        o.z = alpha * acc[i][2] + bvals[2];
        o.w = alpha * acc[i][3] + bvals[3];
        *(float4*)(C + (size_t)(row0 + i) * ldc + col0) = o;
    }
}

// projections: M=4096, N=512, K=512  (grid: (512/BN, 4096/BM))
__global__ void proj_kernel(const float* __restrict__ A, const float* __restrict__ W,
                            const float* __restrict__ bias, float* __restrict__ C)
{
    gemm_nt_core(A, D_MODEL, W, D_MODEL, C, D_MODEL, D_MODEL, 1.0f, bias,
                 blockIdx.y, blockIdx.x);
}

// scores: per (b,h): S = SCALE * Q_h K_h^T  (2048x2048x64), written into attn[b][h][q][k]
__global__ void scores_kernel(float* __restrict__ attn)
{
    const int bh = blockIdx.z;
    const int b = bh >> 3, h = bh & 7;
    const float* A  = g_q + (size_t)b * SEQ * D_MODEL + h * HEAD_DIM;
    const float* Bm = g_k + (size_t)b * SEQ * D_MODEL + h * HEAD_DIM;
    float* C = attn + (size_t)bh * SEQ * SEQ;
    gemm_nt_core(A, D_MODEL, Bm, D_MODEL, C, SEQ, HEAD_DIM, SCALE, nullptr,
                 blockIdx.y, blockIdx.x);
}

// ---------------- top-k(64) + softmax + dense weight write + AV ----------------
__device__ __forceinline__ unsigned fkey(float f) {
    unsigned u = __float_as_uint(f);
    return (u & 0x80000000u) ? ~u : (u | 0x80000000u);
}
__device__ __forceinline__ float fval(unsigned k) {
    unsigned u = (k & 0x80000000u) ? (k & 0x7fffffffu) : ~k;
    return __uint_as_float(u);
}

__global__ void topk_kernel(float* __restrict__ attn, int writeWeights)
{
    const int row = blockIdx.x;                // bh*2048 + q
    const int bh = row >> 11;
    const int q  = row & 2047;
    const int b = bh >> 3, h = bh & 7;
    float* rowp = attn + (size_t)row * SEQ;

    __shared__ unsigned skey[SEQ];
    __shared__ int hist[256];
    __shared__ int scanbuf[256];
    __shared__ unsigned sflags[SEQ / 32];
    __shared__ int   selIdx[TOPK];
    __shared__ float selVal[TOPK];
    __shared__ int s_selBin, s_cntAbove, s_nsel, s_eqcnt;
    __shared__ float s_max, s_sum;
    __shared__ float s_red[256];

    const int tid = threadIdx.x;               // 256

    for (int i = tid; i < SEQ; i += 256) skey[i] = fkey(rowp[i]);
    if (tid < SEQ / 32) sflags[tid] = 0u;
    if (tid == 0) { s_nsel = 0; s_eqcnt = 0; }
    __syncthreads();

    // ---- 4-pass radix select: find 64th-largest key ----
    unsigned prefix = 0u, maskAbove = 0u;
    int need = TOPK;
#pragma unroll
    for (int shift = 24; shift >= 0; shift -= 8) {
        hist[tid] = 0;
        __syncthreads();
        for (int i = tid; i < SEQ; i += 256) {
            unsigned kkey = skey[i];
            bool ok = ((kkey & maskAbove) == prefix);
            int bin = ok ? (int)((kkey >> shift) & 0xffu) : (1024 + (tid & 31));
            unsigned grp = __match_any_sync(0xffffffffu, bin);
            if (ok && ((tid & 31) == (__ffs(grp) - 1)))
                atomicAdd(&hist[bin], __popc(grp));
        }
        __syncthreads();
        // suffix counts via inclusive scan over reversed bins
        scanbuf[tid] = hist[255 - tid];
        __syncthreads();
        for (int off = 1; off < 256; off <<= 1) {
            int t = (tid >= off) ? scanbuf[tid - off] : 0;
            __syncthreads();
            scanbuf[tid] += t;
            __syncthreads();
        }
        int sfx      = scanbuf[255 - tid];                       // count of keys with bin >= tid
        int sfxAbove = (tid == 255) ? 0 : scanbuf[254 - tid];    // count with bin > tid
        if (sfx >= need && sfxAbove < need) {
            s_selBin = tid;
            s_cntAbove = sfxAbove;
        }
        __syncthreads();
        prefix |= ((unsigned)s_selBin) << shift;
        maskAbove |= 0xffu << shift;
        need -= s_cntAbove;
        __syncthreads();
    }
    const unsigned T = prefix;       // exact 64th-largest key
    const int need_eq = need;        // how many ==T entries to keep (>=1)

    // ---- select exactly TOPK entries ----
    for (int i = tid; i < SEQ; i += 256) {
        unsigned kkey = skey[i];
        bool sel = false;
        if (kkey > T) sel = true;
        else if (kkey == T) {
            int r = atomicAdd(&s_eqcnt, 1);
            if (r < need_eq) sel = true;
        }
        if (sel) {
            int p = atomicAdd(&s_nsel, 1);
            selIdx[p] = i;
            selVal[p] = fval(kkey);
            atomicOr(&sflags[i >> 5], 1u << (i & 31));
        }
    }
    __syncthreads();

    // ---- softmax over the 64 kept scores ----
    if (tid == 0) {
        float mm = -INFINITY;
        for (int j = 0; j < TOPK; j++) mm = fmaxf(mm, selVal[j]);
        s_max = mm;
    }
    __syncthreads();
    if (tid < TOPK) selVal[tid] = expf(selVal[tid] - s_max);
    __syncthreads();
    if (tid == 0) {
        float ss = 0.f;
        for (int j = 0; j < TOPK; j++) ss += selVal[j];
        s_sum = ss;
    }
    __syncthreads();
    const float invs = 1.0f / s_sum;

    // ---- dense attn_weights write (in place over the scores) ----
    if (writeWeights) {
        for (int i = tid; i < SEQ; i += 256) {
            bool sel = (sflags[i >> 5] >> (i & 31)) & 1u;
            rowp[i] = sel ? (expf(fval(skey[i]) - s_max) * invs) : 0.0f;
        }
    }

    // ---- AV: out_head[d] = sum_j w_j * V[idx_j][d], d in [0,64) ----
    {
        const int d = tid & 63;
        const int g = tid >> 6;    // 4 groups of 16 terms
        const float* Vb = g_v + (size_t)b * SEQ * D_MODEL + h * HEAD_DIM + d;
        float acc = 0.f;
#pragma unroll
        for (int j = g * 16; j < g * 16 + 16; j++)
            acc += selVal[j] * Vb[(size_t)selIdx[j] * D_MODEL];
        s_red[tid] = acc;
        __syncthreads();
        if (tid < 64) {
            float tot = (s_red[tid] + s_red[tid + 64]) + (s_red[tid + 128] + s_red[tid + 192]);
            g_oh[((size_t)(b * SEQ + q)) * D_MODEL + h * HEAD_DIM + tid] = tot * invs;
        }
    }
}

// ---------------- launch ----------------
extern "C" void kernel_launch(void* const* d_in, const int* in_sizes, int n_in,
                              void* d_out, int out_size)
{
    const float* query = (const float*)d_in[0];
    const float* key   = (const float*)d_in[1];
    const float* value = (const float*)d_in[2];
    const float* wq = (const float*)d_in[3];
    const float* bq = (const float*)d_in[4];
    const float* wk = (const float*)d_in[5];
    const float* bk = (const float*)d_in[6];
    const float* wv = (const float*)d_in[7];
    const float* bv = (const float*)d_in[8];
    const float* wo = (const float*)d_in[9];
    const float* bo = (const float*)d_in[10];
    float* out = (float*)d_out;

    float *pq, *pk, *pv, *poh, *pattn_scratch;
    cudaGetSymbolAddress((void**)&pq,  g_q);
    cudaGetSymbolAddress((void**)&pk,  g_k);
    cudaGetSymbolAddress((void**)&pv,  g_v);
    cudaGetSymbolAddress((void**)&poh, g_oh);
    cudaGetSymbolAddress((void**)&pattn_scratch, g_attn);

    const long long OUT0 = (long long)M_TOT * D_MODEL;                        // 2,097,152
    const long long ATTN = (long long)BATCH * N_HEADS * SEQ * SEQ;            // 67,108,864
    float* attn;
    int writeW;
    if ((long long)out_size >= OUT0 + ATTN) {   // harness concatenates (out, attn_weights)
        attn = out + OUT0;
        writeW = 1;
    } else {                                    // only the first output is checked
        attn = pattn_scratch;
        writeW = 0;
    }

    dim3 gProj(D_MODEL / BN, M_TOT / BM);       // (8, 32)
    proj_kernel<<<gProj, 256>>>(query, wq, bq, pq);
    proj_kernel<<<gProj, 256>>>(key,   wk, bk, pk);
    proj_kernel<<<gProj, 256>>>(value, wv, bv, pv);

    dim3 gScores(SEQ / BN, SEQ / BM, BATCH * N_HEADS);   // (32, 16, 16)
    scores_kernel<<<gScores, 256>>>(attn);

    topk_kernel<<<BATCH * N_HEADS * SEQ, 256>>>(attn, writeW);

    proj_kernel<<<gProj, 256>>>(poh, wo, bo, out);
}

// round 9
// speedup vs baseline: 2.4299x; 2.4299x over previous
#include <cuda_runtime.h>
#include <math.h>

#define D_MODEL 512
#define N_HEADS 8
#define HEAD_DIM 64
#define BATCH 2
#define SEQ 2048
#define TOPK 64
#define M_TOT (BATCH*SEQ)      /* 4096 */
#define SCALE 0.125f

// ---------------- scratch (device globals: allocation-free rule) ----------------
__device__ float g_q[M_TOT * D_MODEL];
__device__ float g_k[M_TOT * D_MODEL];
__device__ float g_v[M_TOT * D_MODEL];
__device__ float g_oh[M_TOT * D_MODEL];
__device__ float g_attn[(size_t)BATCH * N_HEADS * SEQ * SEQ];   // fallback if attn not in d_out

// ---------------- fp32 NT GEMM (projections): 128x64x16, 8x4 per thread ----------------
#define BM 128
#define BN 64
#define BK 16

__device__ __forceinline__ void gemm_nt_core(
    const float* __restrict__ A, int lda,
    const float* __restrict__ Bm, int ldb,
    float* __restrict__ C, int ldc,
    int K, float alpha, const float* __restrict__ bias,
    int bm, int bn)
{
    __shared__ float As[BK][BM];
    __shared__ float Bs[BK][BN];
    const int tid = threadIdx.x;          // 256 threads
    const int ty = tid >> 4;              // 0..15 (row group of 8)
    const int tx = tid & 15;              // 0..15 (col group of 4)

    float acc[8][4];
#pragma unroll
    for (int i = 0; i < 8; i++)
#pragma unroll
        for (int j = 0; j < 4; j++) acc[i][j] = 0.0f;

    const float* Abase = A + (size_t)(bm * BM) * lda;
    const float* Bbase = Bm + (size_t)(bn * BN) * ldb;

    for (int k0 = 0; k0 < K; k0 += BK) {
#pragma unroll
        for (int r = 0; r < 2; r++) {
            int idx = tid + r * 256;
            int row = idx >> 2;
            int kc  = (idx & 3) << 2;
            float4 v = *(const float4*)(Abase + (size_t)row * lda + k0 + kc);
            As[kc + 0][row] = v.x;
            As[kc + 1][row] = v.y;
            As[kc + 2][row] = v.z;
            As[kc + 3][row] = v.w;
        }
        {
            int row = tid >> 2;
            int kc  = (tid & 3) << 2;
            float4 v = *(const float4*)(Bbase + (size_t)row * ldb + k0 + kc);
            Bs[kc + 0][row] = v.x;
            Bs[kc + 1][row] = v.y;
            Bs[kc + 2][row] = v.z;
            Bs[kc + 3][row] = v.w;
        }
        __syncthreads();

#pragma unroll
        for (int kk = 0; kk < BK; kk++) {
            float4 alo = *(const float4*)&As[kk][ty * 8];
            float4 ahi = *(const float4*)&As[kk][ty * 8 + 4];
            float4 bb  = *(const float4*)&Bs[kk][tx * 4];
            float a[8] = {alo.x, alo.y, alo.z, alo.w, ahi.x, ahi.y, ahi.z, ahi.w};
            float b[4] = {bb.x, bb.y, bb.z, bb.w};
#pragma unroll
            for (int i = 0; i < 8; i++)
#pragma unroll
                for (int j = 0; j < 4; j++) acc[i][j] += a[i] * b[j];
        }
        __syncthreads();
    }

    const int row0 = bm * BM + ty * 8;
    const int col0 = bn * BN + tx * 4;
    float bvals[4] = {0.f, 0.f, 0.f, 0.f};
    if (bias) {
        bvals[0] = bias[col0 + 0]; bvals[1] = bias[col0 + 1];
        bvals[2] = bias[col0 + 2]; bvals[3] = bias[col0 + 3];
    }
#pragma unroll
    for (int i = 0; i < 8; i++) {
        float4 o;
        o.x = alpha * acc[i][0] + bvals[0];
        o.y = alpha * acc[i][1] + bvals[1];
        o.z = alpha * acc[i][2] + bvals[2];
        o.w = alpha * acc[i][3] + bvals[3];
        *(float4*)(C + (size_t)(row0 + i) * ldc + col0) = o;
    }
}

// single projection (used for output proj)
__global__ void proj_kernel(const float* __restrict__ A, const float* __restrict__ W,
                            const float* __restrict__ bias, float* __restrict__ C)
{
    gemm_nt_core(A, D_MODEL, W, D_MODEL, C, D_MODEL, D_MODEL, 1.0f, bias,
                 blockIdx.y, blockIdx.x);
}

// fused Q/K/V projections: grid.z in {0,1,2} selects which projection.
__global__ void qkv_proj_kernel(
    const float* __restrict__ inq, const float* __restrict__ ink, const float* __restrict__ inv,
    const float* __restrict__ wq,  const float* __restrict__ wk,  const float* __restrict__ wv,
    const float* __restrict__ bq,  const float* __restrict__ bk,  const float* __restrict__ bv,
    float* __restrict__ oq, float* __restrict__ ok, float* __restrict__ ov)
{
    const float* A; const float* W; const float* bias; float* C;
    if (blockIdx.z == 0)      { A = inq; W = wq; bias = bq; C = oq; }
    else if (blockIdx.z == 1) { A = ink; W = wk; bias = bk; C = ok; }
    else                      { A = inv; W = wv; bias = bv; C = ov; }
    gemm_nt_core(A, D_MODEL, W, D_MODEL, C, D_MODEL, D_MODEL, 1.0f, bias,
                 blockIdx.y, blockIdx.x);
}

// ---------------- scores: per (b,h) S = SCALE * Q K^T, 128x128x16 tile, 8x8 microtile ----------------
#define SBM 128
#define SBN 128
#define SBK 16

__global__ void __launch_bounds__(256) scores_kernel(float* __restrict__ attn)
{
    const int bh = blockIdx.z;
    const int b = bh >> 3, h = bh & 7;
    const float* A  = g_q + (size_t)b * SEQ * D_MODEL + h * HEAD_DIM;
    const float* Bm = g_k + (size_t)b * SEQ * D_MODEL + h * HEAD_DIM;
    float* C = attn + (size_t)bh * SEQ * SEQ;

    __shared__ float As[SBK][SBM];
    __shared__ float Bs[SBK][SBN];
    const int tid = threadIdx.x;
    const int tx = tid & 15;     // col group (8 cols)
    const int ty = tid >> 4;     // row group (8 rows)

    float acc[8][8];
#pragma unroll
    for (int i = 0; i < 8; i++)
#pragma unroll
        for (int j = 0; j < 8; j++) acc[i][j] = 0.0f;

    const float* Abase = A + (size_t)(blockIdx.y * SBM) * D_MODEL;
    const float* Bbase = Bm + (size_t)(blockIdx.x * SBN) * D_MODEL;

#pragma unroll
    for (int k0 = 0; k0 < HEAD_DIM; k0 += SBK) {
#pragma unroll
        for (int r = 0; r < 2; r++) {
            int idx = tid + r * 256;
            int row = idx >> 2;
            int kc  = (idx & 3) << 2;
            float4 v = *(const float4*)(Abase + (size_t)row * D_MODEL + k0 + kc);
            As[kc + 0][row] = v.x; As[kc + 1][row] = v.y;
            As[kc + 2][row] = v.z; As[kc + 3][row] = v.w;
        }
#pragma unroll
        for (int r = 0; r < 2; r++) {
            int idx = tid + r * 256;
            int row = idx >> 2;
            int kc  = (idx & 3) << 2;
            float4 v = *(const float4*)(Bbase + (size_t)row * D_MODEL + k0 + kc);
            Bs[kc + 0][row] = v.x; Bs[kc + 1][row] = v.y;
            Bs[kc + 2][row] = v.z; Bs[kc + 3][row] = v.w;
        }
        __syncthreads();

#pragma unroll
        for (int kk = 0; kk < SBK; kk++) {
            float a[8], bv[8];
            *(float4*)(a)      = *(const float4*)&As[kk][ty * 8];
            *(float4*)(a + 4)  = *(const float4*)&As[kk][ty * 8 + 4];
            *(float4*)(bv)     = *(const float4*)&Bs[kk][tx * 8];
            *(float4*)(bv + 4) = *(const float4*)&Bs[kk][tx * 8 + 4];
#pragma unroll
            for (int i = 0; i < 8; i++)
#pragma unroll
                for (int j = 0; j < 8; j++) acc[i][j] += a[i] * bv[j];
        }
        __syncthreads();
    }

    const int row0 = blockIdx.y * SBM + ty * 8;
    const int col0 = blockIdx.x * SBN + tx * 8;
#pragma unroll
    for (int i = 0; i < 8; i++) {
        float4 o0, o1;
        o0.x = SCALE * acc[i][0]; o0.y = SCALE * acc[i][1];
        o0.z = SCALE * acc[i][2]; o0.w = SCALE * acc[i][3];
        o1.x = SCALE * acc[i][4]; o1.y = SCALE * acc[i][5];
        o1.z = SCALE * acc[i][6]; o1.w = SCALE * acc[i][7];
        *(float4*)(C + (size_t)(row0 + i) * SEQ + col0)     = o0;
        *(float4*)(C + (size_t)(row0 + i) * SEQ + col0 + 4) = o1;
    }
}

// ---------------- top-k(64) + softmax + sparse weight write + AV ----------------
__device__ __forceinline__ unsigned fkey(float f) {
    unsigned u = __float_as_uint(f);
    return (u & 0x80000000u) ? ~u : (u | 0x80000000u);
}
__device__ __forceinline__ float fval(unsigned k) {
    unsigned u = (k & 0x80000000u) ? (k & 0x7fffffffu) : ~k;
    return __uint_as_float(u);
}

#define EQCAP 128

__global__ void __launch_bounds__(256) topk_kernel(float* __restrict__ attn, int writeWeights)
{
    const int row = blockIdx.x;                // bh*2048 + q
    const int bh = row >> 11;
    const int q  = row & 2047;
    const int b = bh >> 3, h = bh & 7;
    float* rowp = attn + (size_t)row * SEQ;

    __shared__ unsigned skey[SEQ];             // 8KB
    __shared__ int hist[256];                  // 1KB
    __shared__ unsigned short listA[SEQ];      // 4KB
    __shared__ unsigned short listB[SEQ];      // 4KB
    __shared__ int   selIdx[TOPK];
    __shared__ float selVal[TOPK];
    __shared__ int   eqIdx[EQCAP];
    __shared__ int s_selBin, s_cntAbove, s_cnt2, s_nsel, s_eqCnt;
    __shared__ float s_part[4];
    __shared__ float s_red[256];

    const int tid = threadIdx.x;               // 256
    const int lane = tid & 31;

    // ---- load row -> monotonic keys (vectorized) ----
    {
        const float4* r4 = (const float4*)rowp;
        for (int i = tid; i < SEQ / 4; i += 256) {
            float4 v = r4[i];
            skey[4*i + 0] = fkey(v.x);
            skey[4*i + 1] = fkey(v.y);
            skey[4*i + 2] = fkey(v.z);
            skey[4*i + 3] = fkey(v.w);
        }
    }
    __syncthreads();

    // ---- zero the output row early: hides the big store behind radix compute ----
    if (writeWeights) {
        float4 z = make_float4(0.f, 0.f, 0.f, 0.f);
        float4* w4 = (float4*)rowp;
        for (int i = tid; i < SEQ / 4; i += 256) w4[i] = z;
    }

    // ---- radix select: exact 64th-largest key ----
    int need = TOPK;
    unsigned prefix = 0u;
    int cnt = SEQ;
    const unsigned short* listIn = 0;
    unsigned short* listOut = listA;

#pragma unroll
    for (int pass = 0; pass < 4; pass++) {
        const int shift = 24 - 8 * pass;
        hist[tid] = 0;
        __syncthreads();

        if (pass == 0) {
            for (int i = tid; i < SEQ; i += 256) {
                int bin = (int)(skey[i] >> 24);
                unsigned grp = __match_any_sync(0xffffffffu, bin);
                if (lane == (__ffs(grp) - 1)) atomicAdd(&hist[bin], __popc(grp));
            }
        } else {
            for (int i = tid; i < cnt; i += 256) {
                int bin = (int)((skey[listIn[i]] >> shift) & 0xffu);
                atomicAdd(&hist[bin], 1);
            }
        }
        __syncthreads();

        // single-warp suffix scan over 256 bins
        if (tid < 32) {
            int base = tid * 8;
            int v[8];
#pragma unroll
            for (int j = 0; j < 8; j++) v[j] = hist[base + j];
            int tot = 0;
#pragma unroll
            for (int j = 0; j < 8; j++) tot += v[j];
            int S = tot;
#pragma unroll
            for (int off = 1; off < 32; off <<= 1) {
                int t = __shfl_down_sync(0xffffffffu, S, off);
                if (tid + off < 32) S += t;
            }
            int run = S - tot;     // count of elements in bins >= base+8
            int fb = -1, fa = 0;
#pragma unroll
            for (int j = 7; j >= 0; j--) {
                int above = run;
                run += v[j];
                if (run >= need && above < need) { fb = base + j; fa = above; }
            }
            if (fb >= 0) { s_selBin = fb; s_cntAbove = fa; }
        }
        __syncthreads();

        const int selBin = s_selBin;
        need -= s_cntAbove;
        prefix |= ((unsigned)selBin) << shift;

        if (pass < 3) {
            if (tid == 0) s_cnt2 = 0;
            __syncthreads();
            if (pass == 0) {
                for (int i = tid; i < SEQ; i += 256)
                    if ((int)(skey[i] >> 24) == selBin) {
                        int p = atomicAdd(&s_cnt2, 1);
                        listOut[p] = (unsigned short)i;
                    }
            } else {
                for (int i = tid; i < cnt; i += 256) {
                    unsigned short idx = listIn[i];
                    if ((int)((skey[idx] >> shift) & 0xffu) == selBin) {
                        int p = atomicAdd(&s_cnt2, 1);
                        listOut[p] = idx;
                    }
                }
            }
            __syncthreads();
            cnt = s_cnt2;
            listIn = listOut;
            listOut = (listOut == listA) ? listB : listA;
        }
    }

    const unsigned T = prefix;     // exact 64th-largest key
    const int need_eq = need;      // how many ==T entries to keep (>=1)

    // ---- gather selected (warp-aggregated compaction: 1 shared atomic per warp) ----
    if (tid == 0) { s_nsel = 0; s_eqCnt = 0; }
    __syncthreads();
    for (int i = tid; i < SEQ; i += 256) {
        unsigned k = skey[i];
        bool gt = (k > T);
        bool eq = (k == T);
        unsigned bal = __ballot_sync(0xffffffffu, gt);
        if (bal) {
            int base = 0;
            int nsel_w = __popc(bal);
            int leader = __ffs(bal) - 1;
            if (lane == leader) base = atomicAdd(&s_nsel, nsel_w);
            base = __shfl_sync(0xffffffffu, base, leader);
            if (gt) {
                int off = __popc(bal & ((1u << lane) - 1u));
                selIdx[base + off] = i;
                selVal[base + off] = fval(k);
            }
        }
        unsigned bale = __ballot_sync(0xffffffffu, eq);
        if (bale) {
            int base = 0;
            int ne = __popc(bale);
            int leader = __ffs(bale) - 1;
            if (lane == leader) base = atomicAdd(&s_eqCnt, ne);
            base = __shfl_sync(0xffffffffu, base, leader);
            if (eq) {
                int off = __popc(bale & ((1u << lane) - 1u));
                if (base + off < EQCAP) eqIdx[base + off] = i;
            }
        }
    }
    __syncthreads();
    // deterministic smallest-index tie selection
    {
        int ec = min(s_eqCnt, EQCAP);
        if (tid < ec) {
            int my = eqIdx[tid];
            int rank = 0;
            for (int j = 0; j < ec; j++) rank += (eqIdx[j] < my);
            if (rank < need_eq) {
                int p = atomicAdd(&s_nsel, 1);
                selIdx[p] = my;
                selVal[p] = fval(T);
            }
        }
    }
    __syncthreads();

    // ---- softmax over the 64 kept scores (parallel) ----
    if (tid < TOPK) {
        float v = selVal[tid];
        float m = v;
#pragma unroll
        for (int off = 16; off > 0; off >>= 1)
            m = fmaxf(m, __shfl_xor_sync(0xffffffffu, m, off));
        if (lane == 0) s_part[tid >> 5] = m;
    }
    __syncthreads();
    const float mx = fmaxf(s_part[0], s_part[1]);
    if (tid < TOPK) {
        float e = __expf(selVal[tid] - mx);
        selVal[tid] = e;
        float s = e;
#pragma unroll
        for (int off = 16; off > 0; off >>= 1)
            s += __shfl_xor_sync(0xffffffffu, s, off);
        if (lane == 0) s_part[2 + (tid >> 5)] = s;
    }
    __syncthreads();
    const float invs = 1.0f / (s_part[2] + s_part[3]);

    // ---- sparse weight scatter (row already zeroed) ----
    if (writeWeights && tid < TOPK)
        rowp[selIdx[tid]] = selVal[tid] * invs;

    // ---- AV: out_head[d] = sum_j w_j * V[idx_j][d] ----
    {
        const int d = tid & 63;
        const int g = tid >> 6;    // 4 groups of 16 terms
        const float* __restrict__ Vb = g_v + (size_t)b * SEQ * D_MODEL + h * HEAD_DIM + d;
        float acc = 0.f;
#pragma unroll
        for (int j = g * 16; j < g * 16 + 16; j++)
            acc += selVal[j] * __ldg(Vb + (size_t)selIdx[j] * D_MODEL);
        s_red[tid] = acc;
        __syncthreads();
        if (tid < 64) {
            float tot = (s_red[tid] + s_red[tid + 64]) + (s_red[tid + 128] + s_red[tid + 192]);
            g_oh[((size_t)(b * SEQ + q)) * D_MODEL + h * HEAD_DIM + tid] = tot * invs;
        }
    }
}

// ---------------- launch ----------------
extern "C" void kernel_launch(void* const* d_in, const int* in_sizes, int n_in,
                              void* d_out, int out_size)
{
    const float* query = (const float*)d_in[0];
    const float* key   = (const float*)d_in[1];
    const float* value = (const float*)d_in[2];
    const float* wq = (const float*)d_in[3];
    const float* bq = (const float*)d_in[4];
    const float* wk = (const float*)d_in[5];
    const float* bk = (const float*)d_in[6];
    const float* wv = (const float*)d_in[7];
    const float* bv = (const float*)d_in[8];
    const float* wo = (const float*)d_in[9];
    const float* bo = (const float*)d_in[10];
    float* out = (float*)d_out;

    float *pq, *pk, *pv, *poh, *pattn_scratch;
    cudaGetSymbolAddress((void**)&pq,  g_q);
    cudaGetSymbolAddress((void**)&pk,  g_k);
    cudaGetSymbolAddress((void**)&pv,  g_v);
    cudaGetSymbolAddress((void**)&poh, g_oh);
    cudaGetSymbolAddress((void**)&pattn_scratch, g_attn);

    const long long OUT0 = (long long)M_TOT * D_MODEL;
    const long long ATTN = (long long)BATCH * N_HEADS * SEQ * SEQ;
    float* attn;
    int writeW;
    if ((long long)out_size >= OUT0 + ATTN) {
        attn = out + OUT0;
        writeW = 1;
    } else {
        attn = pattn_scratch;
        writeW = 0;
    }

    dim3 gQKV(D_MODEL / BN, M_TOT / BM, 3);     // (8, 32, 3) = 768 blocks, one launch
    qkv_proj_kernel<<<gQKV, 256>>>(query, key, value, wq, wk, wv, bq, bk, bv, pq, pk, pv);

    dim3 gScores(SEQ / SBN, SEQ / SBM, BATCH * N_HEADS);   // (16, 16, 16)
    scores_kernel<<<gScores, 256>>>(attn);

    topk_kernel<<<BATCH * N_HEADS * SEQ, 256>>>(attn, writeW);

    dim3 gProj(D_MODEL / BN, M_TOT / BM);       // (8, 32)
    proj_kernel<<<gProj, 256>>>(poh, wo, bo, out);
}